// round 6
// baseline (speedup 1.0000x reference)
#include <cuda_runtime.h>
#include <cuda_fp16.h>
#include <cstdint>

#define N_OUT  11008
#define K_IN   4096
#define M_TOK  32
#define KSPLIT 4
#define K_CTA  1024   // K per CTA
#define N_CTA  128    // out channels per CTA (8 warps x 16)
#define NT     2      // n-tiles (of 8 channels) per warp

// Split-K fp32 partials: [KSPLIT][M_TOK][N_OUT] (~5.6 MB)
__device__ float g_scratch[KSPLIT * M_TOK * N_OUT];

__device__ __forceinline__ void mma16816(float c[4],
                                         unsigned a0, unsigned a1, unsigned a2, unsigned a3,
                                         unsigned b0, unsigned b1) {
    asm volatile(
        "mma.sync.aligned.m16n8k16.row.col.f32.f16.f16.f32 "
        "{%0,%1,%2,%3}, {%4,%5,%6,%7}, {%8,%9}, {%0,%1,%2,%3};\n"
        : "+f"(c[0]), "+f"(c[1]), "+f"(c[2]), "+f"(c[3])
        : "r"(a0), "r"(a1), "r"(a2), "r"(a3), "r"(b0), "r"(b1));
}

// Pack byte0 of four int32s (sign pattern irrelevant: low byte == int8 bits)
__device__ __forceinline__ unsigned pack4(int4 v) {
    unsigned t0 = __byte_perm((unsigned)v.x, (unsigned)v.y, 0x0040);
    unsigned t1 = __byte_perm((unsigned)v.z, (unsigned)v.w, 0x0040);
    return __byte_perm(t0, t1, 0x5410);  // {x.b0, y.b0, z.b0, w.b0}
}

// k-permutation (audited): thread (g=lane/4, tg=lane%4) owns logical
// k = tg*16 + {0..15} within each k64 chunk. MMA step s uses logical
// k = tg*16+4s+{0,1} at hw slots {2tg,2tg+1} and +{2,3} at {2tg+8,2tg+9}.
// A fragments from smem use the identical map, so the k-sum is exact.
__global__ void __launch_bounds__(256, 2)
qlinear_main(const float* __restrict__ x, const int* __restrict__ qw) {
    extern __shared__ __align__(16) unsigned char smem[];
    const int t  = threadIdx.x;
    const int k0 = blockIdx.y * K_CTA;

    // ---- Stage x slice [32][1024] fp32 -> fp16 smem, XOR-swizzled 16B units ----
    // smem offset = row*2048 + b*128 + ((u ^ (row&7)) << 4);  b = k64 chunk, u = 8-half unit
#pragma unroll
    for (int i = 0; i < 16; ++i) {
        int unit = i * 256 + t;          // 4096 units total (32 rows x 128)
        int row  = unit >> 7;
        int w    = unit & 127;
        int b    = w >> 3, u = w & 7;
        const float* src = x + (size_t)row * K_IN + k0 + b * 64 + u * 8;
        float4 f0 = *reinterpret_cast<const float4*>(src);
        float4 f1 = *reinterpret_cast<const float4*>(src + 4);
        __half2 h0 = __floats2half2_rn(f0.x, f0.y);
        __half2 h1 = __floats2half2_rn(f0.z, f0.w);
        __half2 h2 = __floats2half2_rn(f1.x, f1.y);
        __half2 h3 = __floats2half2_rn(f1.z, f1.w);
        uint4 v;
        v.x = *reinterpret_cast<unsigned*>(&h0);
        v.y = *reinterpret_cast<unsigned*>(&h1);
        v.z = *reinterpret_cast<unsigned*>(&h2);
        v.w = *reinterpret_cast<unsigned*>(&h3);
        *reinterpret_cast<uint4*>(smem + row * 2048 + b * 128 + ((u ^ (row & 7)) << 4)) = v;
    }
    __syncthreads();

    const int warp = t >> 5, lane = t & 31;
    const int g = lane >> 2, tg = lane & 3;
    const int nbase = blockIdx.x * N_CTA + warp * (NT * 8);
    const int* wp = qw + (size_t)(nbase + g) * K_IN + k0 + tg * 16;

    float c[NT][2][4];
#pragma unroll
    for (int nt = 0; nt < NT; nt++)
#pragma unroll
        for (int mh = 0; mh < 2; mh++)
#pragma unroll
            for (int q = 0; q < 4; q++) c[nt][mh][q] = 0.f;

    // Preload first k64 chunk of weights: per nt, 4 x uint4 (16 int32 = 16 k)
    int4 bcur[NT][4];
#pragma unroll
    for (int nt = 0; nt < NT; nt++)
#pragma unroll
        for (int s = 0; s < 4; s++)
            bcur[nt][s] = *reinterpret_cast<const int4*>(wp + (size_t)nt * 8 * K_IN + s * 4);

    const __half2 magic = __halves2half2(__ushort_as_half(0x6480), __ushort_as_half(0x6480)); // 1152

#pragma unroll 1
    for (int kc = 0; kc < 16; ++kc) {
        int4 bnext[NT][4];
        if (kc < 15) {
#pragma unroll
            for (int nt = 0; nt < NT; nt++)
#pragma unroll
                for (int s = 0; s < 4; s++)
                    bnext[nt][s] = *reinterpret_cast<const int4*>(
                        wp + (kc + 1) * 64 + (size_t)nt * 8 * K_IN + s * 4);
        }

        // A fragments: 4 row-groups (tokens g+8r), 16 halves each from swizzled smem
        unsigned A[4][8];
#pragma unroll
        for (int r = 0; r < 4; ++r) {
            int row = g + 8 * r;
            const unsigned char* base = smem + row * 2048 + kc * 128;
            uint4 lo = *reinterpret_cast<const uint4*>(base + (((tg * 2 + 0) ^ g) << 4));
            uint4 hi = *reinterpret_cast<const uint4*>(base + (((tg * 2 + 1) ^ g) << 4));
            A[r][0] = lo.x; A[r][1] = lo.y; A[r][2] = lo.z; A[r][3] = lo.w;
            A[r][4] = hi.x; A[r][5] = hi.y; A[r][6] = hi.z; A[r][7] = hi.w;
        }

#pragma unroll
        for (int nt = 0; nt < NT; nt++) {
#pragma unroll
            for (int s = 0; s < 4; s++) {
                unsigned packed = pack4(bcur[nt][s]);   // 4 int8 bytes, logical k tg*16+4s+{0..3}
                unsigned ts = packed ^ 0x80808080u;
                unsigned lo = __byte_perm(ts, 0x64646464u, 0x4140);
                unsigned hi = __byte_perm(ts, 0x64646464u, 0x4342);
                __half2 b0h = __hsub2(*reinterpret_cast<__half2*>(&lo), magic);
                __half2 b1h = __hsub2(*reinterpret_cast<__half2*>(&hi), magic);
                unsigned b0 = *reinterpret_cast<unsigned*>(&b0h);
                unsigned b1 = *reinterpret_cast<unsigned*>(&b1h);
                mma16816(c[nt][0], A[0][2 * s], A[1][2 * s], A[0][2 * s + 1], A[1][2 * s + 1], b0, b1);
                mma16816(c[nt][1], A[2][2 * s], A[3][2 * s], A[2][2 * s + 1], A[3][2 * s + 1], b0, b1);
            }
        }
        if (kc < 15) {
#pragma unroll
            for (int nt = 0; nt < NT; nt++)
#pragma unroll
                for (int s = 0; s < 4; s++) bcur[nt][s] = bnext[nt][s];
        }
    }

    // ---- fp32 partials, each slot written exactly once ----
    float* sp = g_scratch + (size_t)blockIdx.y * (M_TOK * N_OUT);
#pragma unroll
    for (int nt = 0; nt < NT; nt++) {
        int n = nbase + nt * 8 + tg * 2;
#pragma unroll
        for (int mh = 0; mh < 2; mh++) {
            int tok = mh * 16 + g;
            *reinterpret_cast<float2*>(sp + (size_t)tok * N_OUT + n) =
                make_float2(c[nt][mh][0], c[nt][mh][1]);
            *reinterpret_cast<float2*>(sp + (size_t)(tok + 8) * N_OUT + n) =
                make_float2(c[nt][mh][2], c[nt][mh][3]);
        }
    }
}

// Epilogue: sum KSPLIT partials, apply per-channel scale + bias, fp32 out.
__global__ void qlinear_epi(const float* __restrict__ scales,
                            const float* __restrict__ bias,
                            float* __restrict__ out) {
    int idx = blockIdx.x * 256 + threadIdx.x;            // pair index
    if (idx >= M_TOK * N_OUT / 2) return;
    int tok = idx / (N_OUT / 2);
    int n   = (idx % (N_OUT / 2)) * 2;
    const float* sp = g_scratch + (size_t)tok * N_OUT + n;
    float2 a = *reinterpret_cast<const float2*>(sp);
    float2 b = *reinterpret_cast<const float2*>(sp + (size_t)1 * M_TOK * N_OUT);
    float2 d = *reinterpret_cast<const float2*>(sp + (size_t)2 * M_TOK * N_OUT);
    float2 e = *reinterpret_cast<const float2*>(sp + (size_t)3 * M_TOK * N_OUT);
    float s0 = a.x + b.x + d.x + e.x;
    float s1 = a.y + b.y + d.y + e.y;
    float2 sc = *reinterpret_cast<const float2*>(scales + n);
    float2 bi = *reinterpret_cast<const float2*>(bias + n);
    float2 o = make_float2(s0 * sc.x + bi.x, s1 * sc.y + bi.y);
    *reinterpret_cast<float2*>(out + (size_t)tok * N_OUT + n) = o;
}

extern "C" void kernel_launch(void* const* d_in, const int* in_sizes, int n_in,
                              void* d_out, int out_size) {
    const float* x      = (const float*)d_in[0];
    const int*   qw     = (const int*)d_in[1];
    const float* scales = (const float*)d_in[2];
    const float* bias   = (const float*)d_in[3];
    float*       out    = (float*)d_out;

    cudaFuncSetAttribute((const void*)qlinear_main,
                         cudaFuncAttributeMaxDynamicSharedMemorySize, 65536);
    qlinear_main<<<dim3(N_OUT / N_CTA, KSPLIT), 256, 65536>>>(x, qw);
    qlinear_epi<<<(M_TOK * N_OUT / 2 + 255) / 256, 256>>>(scales, bias, out);
}